// round 11
// baseline (speedup 1.0000x reference)
#include <cuda_runtime.h>
#include <math.h>

// Problem constants
#define Bx 16
#define Nx 512
#define Fx 256
#define BNx (Bx*Nx)      // 8192 rows total
#define KC 32            // N_CONCEPTS
#define KM_ITERS 10
#define CC_ITERS 20

// Output packing, float-element offsets (valid for BOTH layouts for x_new/adj/conc/h):
// x_new (B,N,F) | adj_new (B,N,N) | concepts (B,N) | h (B,N,F) | mask_new (B,N)
#define XNEW_OFF 0L
#define ADJ_OFF  (XNEW_OFF + (long)BNx*Fx)            // 2097152
#define CONC_OFF (ADJ_OFF  + (long)BNx*Nx)            // 6291456
#define H_OFF    (CONC_OFF + (long)BNx)               // 6299648
#define MASKF_OFF (H_OFF   + (long)BNx*Fx)            // 8396800 (float layout)
#define MASKB_OFF (H_OFF*4L + (long)BNx*Fx*4L)        // 33587200 byte offset (byte layout)

// ---------------- scratch (device globals; no allocation allowed) ----------
__device__ float g_xw   [BNx*Fx];        // X@W
__device__ float g_h1   [BNx*Fx];        // layer-1 output
__device__ float g_anorm[(long)BNx*Nx];  // normalized adjacency; reused as adj_r
__device__ float g_deg [BNx];
__device__ float g_cent[KC*Fx];
__device__ int   g_assign[BNx];
__device__ float g_part[KC*8*Fx];
__device__ int   g_pcnt[KC*8];
__device__ unsigned g_bits[BNx*16];
__device__ int   g_seg[BNx];
__device__ int   g_nc[Bx];

// ---------------- degree: d = (1 + sum_j adj[i,j])^-0.5 --------------------
// adj entries are exact 0/1 -> sum is exact in any order.
__global__ void deg_kernel(const float* __restrict__ adj) {
    int row  = blockIdx.x * 8 + (threadIdx.x >> 5);
    int lane = threadIdx.x & 31;
    const float* r = adj + (long)row * Nx;
    float s = 0.f;
    #pragma unroll 4
    for (int j = lane; j < Nx; j += 32) s += r[j];
    for (int o = 16; o; o >>= 1) s += __shfl_xor_sync(~0u, s, o);
    if (lane == 0) {
        float t = s + 1.0f;
        if (t < 1.0f) t = 1.0f;
        g_deg[row] = 1.0f / sqrtf(t);
    }
}

// ---------------- a_norm[b,i,j] = (d_i * (adj+I)) * d_j --------------------
// Matches ref rounding: (d_i * a) * d_j, left-assoc.
__global__ void anorm_kernel(const float* __restrict__ adj) {
    long idx = (long)blockIdx.x * 256 + threadIdx.x;
    int  j   = (int)(idx & 511);
    long row = idx >> 9;              // b*512 + i
    int  i   = (int)(row & 511);
    float a = adj[idx] + ((i == j) ? 1.0f : 0.0f);
    float t = g_deg[row] * a;
    g_anorm[idx] = t * g_deg[(row & ~511L) + j];
}

// ---------------- naive row GEMM: C[row,f] = sum_k A[row,k]*W[k,f] ---------
// One block per row; sequential k; obviously correct.
__global__ __launch_bounds__(256) void rowgemm_kernel(const float* __restrict__ A,
                                                      const float* __restrict__ W,
                                                      float* __restrict__ C) {
    __shared__ float sa[Fx];
    int row = blockIdx.x, f = threadIdx.x;
    sa[f] = A[(long)row * Fx + f];
    __syncthreads();
    float acc = 0.f;
    #pragma unroll 8
    for (int k = 0; k < Fx; k++) acc = fmaf(sa[k], W[k * Fx + f], acc);
    C[(long)row * Fx + f] = acc;
}

// ---------------- naive agg: dst = relu(anorm_row @ xw + bias) -------------
__global__ __launch_bounds__(256) void rowagg_kernel(const float* __restrict__ xw,
                                                     const float* __restrict__ bias,
                                                     float* __restrict__ dst) {
    __shared__ float sa[Nx];
    int row = blockIdx.x, f = threadIdx.x;
    long bb = row & ~511L;
    sa[f]       = g_anorm[(long)row * Nx + f];
    sa[f + 256] = g_anorm[(long)row * Nx + f + 256];
    __syncthreads();
    float acc = 0.f;
    #pragma unroll 8
    for (int j = 0; j < Nx; j++) acc = fmaf(sa[j], xw[(bb + j) * Fx + f], acc);
    float v = acc + bias[f];
    dst[(long)row * Fx + f] = v > 0.f ? v : 0.f;
}

// ---------------- centroid init: cent = pts[:32] ---------------------------
__global__ void centinit_kernel(const float* __restrict__ pts) {
    int i = blockIdx.x * 256 + threadIdx.x;
    g_cent[i] = pts[i];
}

// ---------------- kmeans assignment: thread per (point, centroid) ----------
// d2 = (p2 - 2*dot) + c2, all sums sequential over k (ascending).
// Warp = one point, lane = centroid. Exact first-min tie-break.
__global__ __launch_bounds__(256) void kmeans_assign(const float* __restrict__ pts,
                                                     void* conc_out, int conc_int) {
    __shared__ float sct[KC * Fx];   // transposed: sct[k*32 + c]
    int tid = threadIdx.x;
    for (int i = tid; i < KC * Fx; i += 256) {
        int k = i >> 5, c = i & 31;
        sct[i] = g_cent[c * Fx + k];
    }
    __syncthreads();

    int p = blockIdx.x * 8 + (tid >> 5);
    int c = tid & 31;
    const float* pr = pts + (long)p * Fx;

    float p2 = 0.f, c2 = 0.f, dot = 0.f;
    #pragma unroll 8
    for (int k = 0; k < Fx; k++) {
        float xv = pr[k];
        float cv = sct[k * KC + c];
        p2  = fmaf(xv, xv, p2);
        c2  = fmaf(cv, cv, c2);
        dot = fmaf(xv, cv, dot);
    }
    float d2 = (p2 - 2.0f * dot) + c2;
    int bc = c;
    for (int o = 16; o; o >>= 1) {
        float od2 = __shfl_xor_sync(~0u, d2, o);
        int   oc  = __shfl_xor_sync(~0u, bc, o);
        if (od2 < d2 || (od2 == d2 && oc < bc)) { d2 = od2; bc = oc; }
    }
    if (c == 0) {
        g_assign[p] = bc;
        if (conc_out) {
            if (conc_int) ((int*)conc_out)[p] = bc;
            else          ((float*)conc_out)[p] = (float)bc;
        }
    }
}

// ---------------- kmeans partial sums (deterministic, ascending) -----------
__global__ __launch_bounds__(256) void kmeans_part(const float* __restrict__ pts) {
    int k = blockIdx.x, chunk = blockIdx.y;   // grid (32, 8)
    __shared__ int sa[1024];
    int tid = threadIdx.x;
    for (int i = tid; i < 1024; i += 256) sa[i] = g_assign[chunk * 1024 + i];
    __syncthreads();
    int base = chunk * 1024;
    float s = 0.f; int cnt = 0;
    for (int p = 0; p < 1024; p++) {
        if (sa[p] == k) { s += pts[(long)(base + p) * Fx + tid]; cnt++; }
    }
    g_part[(k * 8 + chunk) * Fx + tid] = s;
    if (tid == 0) g_pcnt[k * 8 + chunk] = cnt;
}

__global__ void kmeans_upd() {
    int k = blockIdx.x, f = threadIdx.x;
    float s = 0.f; int cnt = 0;
    #pragma unroll
    for (int c = 0; c < 8; c++) s += g_part[(k * 8 + c) * Fx + f];
    #pragma unroll
    for (int c = 0; c < 8; c++) cnt += g_pcnt[k * 8 + c];
    if (cnt > 0) g_cent[k * Fx + f] = s / (float)cnt;
}

// ---------------- same-concept adjacency bitmask ---------------------------
__global__ void bits_kernel(const float* __restrict__ adj) {
    int gw = blockIdx.x * 8 + (threadIdx.x >> 5);
    int lane = threadIdx.x & 31;
    int w = gw & 15;
    int row = gw >> 4;                // b*512 + i
    int b = row >> 9;
    int j = w * 32 + lane;
    float a = adj[(long)row * Nx + j];
    int ci = g_assign[row];
    int cj = g_assign[(b << 9) + j];
    unsigned m = __ballot_sync(~0u, (a > 0.f) && (ci == cj));
    if (lane == 0) g_bits[row * 16 + w] = m;
}

// ---------------- connected components (one block per batch) ---------------
__global__ __launch_bounds__(512) void cc_kernel() {
    __shared__ int lab[512];
    __shared__ int tmp[512];
    int b = blockIdx.x, i = threadIdx.x;
    lab[i] = i;
    unsigned wc[16];
    const unsigned* rb = &g_bits[((long)(b << 9) + i) * 16];
    #pragma unroll
    for (int w = 0; w < 16; w++) wc[w] = rb[w];
    __syncthreads();

    for (int it = 0; it < CC_ITERS; it++) {
        int m = lab[i];
        #pragma unroll
        for (int w = 0; w < 16; w++) {
            unsigned bits = wc[w];
            while (bits) {
                int j = w * 32 + __ffs((int)bits) - 1;
                bits &= bits - 1;
                int lj = lab[j];
                if (lj < m) m = lj;
            }
        }
        __syncthreads();
        lab[i] = m;
        __syncthreads();
        tmp[i] = lab[lab[i]];
        __syncthreads();
        lab[i] = tmp[tmp[i]];
        __syncthreads();
    }
    tmp[i] = (lab[i] == i) ? 1 : 0;
    __syncthreads();
    for (int off = 1; off < 512; off <<= 1) {
        int v = tmp[i] + ((i >= off) ? tmp[i - off] : 0);
        __syncthreads();
        tmp[i] = v;
        __syncthreads();
    }
    g_seg[(b << 9) + i] = tmp[lab[i]];
    if (i == 511) g_nc[b] = tmp[511];
}

// ---------------- mask_new writeback (both layouts) ------------------------
__global__ void mask_kernel(void* mout, int bytemode) {
    int idx = blockIdx.x * 256 + threadIdx.x;   // over BNx
    int b = idx >> 9, i = idx & 511;
    int v = (i < g_nc[b]) ? 1 : 0;
    if (bytemode) ((unsigned char*)mout)[idx] = (unsigned char)v;
    else          ((float*)mout)[idx] = (float)v;
}

// ---------------- x_new: segment-sum of h (ascending i) --------------------
__global__ __launch_bounds__(256) void xnew_kernel(const float* __restrict__ h,
                                                   float* __restrict__ out) {
    int r = blockIdx.x, b = blockIdx.y;
    __shared__ int ss[512];
    int f = threadIdx.x;
    for (int i = f; i < 512; i += 256) ss[i] = g_seg[(b << 9) + i];
    __syncthreads();
    float acc = 0.f;
    int tgt = r + 1;
    for (int i = 0; i < 512; i++) {
        if (ss[i] == tgt) acc += h[((long)(b << 9) + i) * Fx + f];
    }
    out[((long)(b << 9) + r) * Fx + f] = acc;
}

// ---------------- adj_new: binary scatter (adj entries exactly 0/1) --------
__global__ void zero2_kernel(float* __restrict__ outAdj) {
    long idx = (long)blockIdx.x * 256 + threadIdx.x;
    g_anorm[idx] = 0.f;   // reuse as adj_r
    outAdj[idx] = 0.f;
}
__global__ void adjrowA_kernel(const float* __restrict__ adj) {
    long idx = (long)blockIdx.x * 256 + threadIdx.x;  // b*N*N + i*N + j
    if (adj[idx] > 0.f) {
        int  j   = (int)(idx & 511);
        long row = idx >> 9;
        long bb  = row & ~511L;
        int  s   = g_seg[row];
        g_anorm[(bb + s - 1) * Nx + j] = 1.0f;
    }
}
__global__ void adjrowB_kernel(float* __restrict__ outAdj) {
    long idx = (long)blockIdx.x * 256 + threadIdx.x;  // b*N*N + r*N + j
    if (g_anorm[idx] > 0.f) {
        int  j   = (int)(idx & 511);
        long row = idx >> 9;
        long bb  = row & ~511L;
        int  c   = g_seg[bb + j];
        outAdj[row * Nx + c - 1] = 1.0f;
    }
}

// ---------------------------------------------------------------------------
extern "C" void kernel_launch(void* const* d_in, const int* in_sizes, int n_in,
                              void* d_out, int out_size) {
    // Size-based input routing (robust to metadata ordering)
    const float *x = 0, *adj = 0, *W1 = 0, *b1 = 0, *W2 = 0, *b2 = 0;
    for (int i = 0; i < n_in; i++) {
        long s = in_sizes[i];
        const float* p = (const float*)d_in[i];
        if      (s == (long)BNx * Fx) { if (!x)  x  = p; }
        else if (s == (long)BNx * Nx) { if (!adj) adj = p; }
        else if (s == (long)Fx * Fx)  { if (!W1) W1 = p; else if (!W2) W2 = p; }
        else if (s == (long)Fx)       { if (!b1) b1 = p; else if (!b2) b2 = p; }
    }
    if (!x || !adj || !W1 || !b1 || !W2 || !b2) {
        x   = (const float*)d_in[0];
        adj = (const float*)d_in[1];
        W1  = (const float*)d_in[3];
        b1  = (const float*)d_in[4];
        W2  = (const float*)d_in[5];
        b2  = (const float*)d_in[6];
    }

    // Output layout detection via out_size:
    //   8404992 -> all outputs stored as float32 elements
    //   8398848 -> byte-packed: concepts int32 bits, mask_new bool bytes
    int bytemode = (out_size == 8398848) ? 1 : 0;

    float* out  = (float*)d_out;
    float* h    = out + H_OFF;
    void*  conc = (void*)(out + CONC_OFF);
    void*  mptr = bytemode ? (void*)((unsigned char*)d_out + MASKB_OFF)
                           : (void*)(out + MASKF_OFF);

    int nnBlocks = (int)(((long)BNx * Nx) / 256);   // 16384

    deg_kernel<<<BNx / 8, 256>>>(adj);
    anorm_kernel<<<nnBlocks, 256>>>(adj);

    // Layer 1: xw = x@W1; h1 = relu(anorm@xw + b1)
    rowgemm_kernel<<<BNx, 256>>>(x, W1, g_xw);
    rowagg_kernel<<<BNx, 256>>>(g_xw, b1, g_h1);

    // Layer 2
    rowgemm_kernel<<<BNx, 256>>>(g_h1, W2, g_xw);
    rowagg_kernel<<<BNx, 256>>>(g_xw, b2, h);

    // K-means (pure fp32, sequential-k reductions, exact first-min argmin)
    centinit_kernel<<<KC * Fx / 256, 256>>>(h);
    for (int it = 0; it < KM_ITERS; it++) {
        kmeans_assign<<<BNx / 8, 256>>>(h, 0, 0);
        kmeans_part<<<dim3(KC, 8), 256>>>(h);
        kmeans_upd<<<KC, Fx>>>();
    }
    kmeans_assign<<<BNx / 8, 256>>>(h, conc, bytemode);

    // Connected components on same-concept subgraph
    bits_kernel<<<BNx * 16 / 8, 256>>>(adj);
    cc_kernel<<<Bx, 512>>>();
    mask_kernel<<<BNx / 256, 256>>>(mptr, bytemode);

    // Coarsening
    xnew_kernel<<<dim3(Nx, Bx), 256>>>(h, out + XNEW_OFF);
    zero2_kernel<<<nnBlocks, 256>>>(out + ADJ_OFF);
    adjrowA_kernel<<<nnBlocks, 256>>>(adj);
    adjrowB_kernel<<<nnBlocks, 256>>>(out + ADJ_OFF);
}